// round 7
// baseline (speedup 1.0000x reference)
#include <cuda_runtime.h>
#include <cuda_bf16.h>
#include <cstdint>

#define E_NUM   8
#define N_TOK   8192
#define D_MOD   1024
#define THRESH  0.0f
#define RES_DST 0
#define ROWS_PER_BLOCK 8
#define NBLOCKS ((E_NUM * N_TOK) / ROWS_PER_BLOCK)
#define CHUNK_TOK 1024            /* tokens per setup block */
#define SETUP_THREADS 256
#define TOK_PER_THR (CHUNK_TOK / SETUP_THREADS)   /* 4 */

// Scratch (allocation-free rule: __device__ globals)
__device__ int g_src[E_NUM * N_TOK];   // inverse map: expert e, slot s -> source token
__device__ int g_loads[E_NUM];         // tokens per expert

// ---------------------------------------------------------------------------
// Setup: 8 clusters (one per expert) x 8 CTAs (one per 1024-token chunk).
// Chunk totals exchanged via DSMEM around a cluster barrier -> global prefix.
// ---------------------------------------------------------------------------
__global__ void __launch_bounds__(SETUP_THREADS) __cluster_dims__(8, 1, 1)
setup_kernel(const float* __restrict__ gates) {
    const int t = threadIdx.x;
    const int lane = t & 31;
    const int wid  = t >> 5;                 // 0..7
    unsigned int rank;
    asm("mov.u32 %0, %%cluster_ctarank;" : "=r"(rank));   // chunk id 0..7
    const int e = blockIdx.x >> 3;                         // cluster id = expert

    const int tok0 = (int)rank * CHUNK_TOK + t * TOK_PER_THR;

    unsigned int bits = 0;
    #pragma unroll
    for (int i = 0; i < TOK_PER_THR; i++) {
        const float4* gp = (const float4*)(gates + (size_t)(tok0 + i) * E_NUM);
        float4 a = gp[0];
        float4 b = gp[1];
        float g[8] = {a.x, a.y, a.z, a.w, b.x, b.y, b.z, b.w};
        bool m = g[e] > THRESH;
        if (e == RES_DST) {
            bool any = false;
            #pragma unroll
            for (int k = 0; k < 8; k++) any |= (g[k] > THRESH);
            if (!any) m = true;   // residual routing
        }
        bits |= (m ? 1u : 0u) << i;
    }
    const int cnt = __popc(bits);

    int incl = cnt;
    #pragma unroll
    for (int o = 1; o < 32; o <<= 1) {
        int v = __shfl_up_sync(0xffffffffu, incl, o);
        if (lane >= o) incl += v;
    }

    __shared__ int wtot[8];
    __shared__ int wexc[8];
    __shared__ int s_total;      // this CTA's chunk total (DSMEM-exported)
    __shared__ int peer[8];      // peers' chunk totals
    if (lane == 31) wtot[wid] = incl;
    __syncthreads();
    if (t == 0) {
        int run = 0;
        #pragma unroll
        for (int r = 0; r < 8; r++) { int v = wtot[r]; wexc[r] = run; run += v; }
        s_total = run;
    }
    __syncthreads();

    asm volatile("barrier.cluster.arrive.aligned;" ::: "memory");
    asm volatile("barrier.cluster.wait.aligned;"   ::: "memory");

    if (t < 8) {
        unsigned int laddr;
        asm("{ .reg .u64 tt; cvta.to.shared.u64 tt, %1; cvt.u32.u64 %0, tt; }"
            : "=r"(laddr) : "l"(&s_total));
        unsigned int raddr;
        asm("mapa.shared::cluster.u32 %0, %1, %2;" : "=r"(raddr) : "r"(laddr), "r"(t));
        int v;
        asm volatile("ld.shared::cluster.u32 %0, [%1];" : "=r"(v) : "r"(raddr));
        peer[t] = v;
    }
    __syncthreads();

    asm volatile("barrier.cluster.arrive.aligned;" ::: "memory");

    int base = 0, tot = 0;
    #pragma unroll
    for (int r = 0; r < 8; r++) {
        int v = peer[r];
        if (r < (int)rank) base += v;
        tot += v;
    }
    if (rank == 0 && t == 0) g_loads[e] = tot;

    int off = base + wexc[wid] + (incl - cnt);
    #pragma unroll
    for (int i = 0; i < TOK_PER_THR; i++) {
        if (bits & (1u << i)) {
            g_src[e * N_TOK + off] = tok0 + i;
            off++;
        }
    }

    asm volatile("barrier.cluster.wait.aligned;" ::: "memory");
}

// ---------------------------------------------------------------------------
// Scatter (PDL consumer): 8 rows per block, front-batched loads (MLP=8),
// streaming __stcs stores.
// ---------------------------------------------------------------------------
__global__ void __launch_bounds__(256) scatter_kernel(const float* __restrict__ in_flow,
                                                      float* __restrict__ out,
                                                      int out_size) {
#if __CUDA_ARCH__ >= 900
    cudaGridDependencySynchronize();   // HW wait for setup_kernel completion
#endif

    const int row0 = blockIdx.x * ROWS_PER_BLOCK;   // aligned: rows share one expert
    const int e    = row0 >> 13;                    // / N_TOK
    const int s0   = row0 & (N_TOK - 1);
    const int load = g_loads[e];
    const int tid  = threadIdx.x;

    int  src[ROWS_PER_BLOCK];
    bool val[ROWS_PER_BLOCK];
    #pragma unroll
    for (int i = 0; i < ROWS_PER_BLOCK; i++) {
        val[i] = (s0 + i) < load;
        src[i] = val[i] ? g_src[row0 + i] : 0;
    }

    // Front-batched independent loads (MLP = 8 per thread).
    float4 v[ROWS_PER_BLOCK];
    #pragma unroll
    for (int i = 0; i < ROWS_PER_BLOCK; i++) {
        if (val[i]) {
            const float4* ip = (const float4*)(in_flow + (size_t)src[i] * D_MOD);
            v[i] = ip[tid];
        } else {
            v[i] = make_float4(0.f, 0.f, 0.f, 0.f);
        }
    }

    // Streaming stores: evict-first so in_flow stays L2-resident.
    #pragma unroll
    for (int i = 0; i < ROWS_PER_BLOCK; i++) {
        float4* op = (float4*)(out + (size_t)(row0 + i) * D_MOD);
        __stcs(op + tid, v[i]);
    }

    const long long base = (long long)E_NUM * N_TOK * D_MOD;
    if (blockIdx.x == 0 && tid < E_NUM && base + E_NUM <= (long long)out_size) {
        out[base + tid] = (float)g_loads[tid];
    }
}

extern "C" void kernel_launch(void* const* d_in, const int* in_sizes, int n_in,
                              void* d_out, int out_size) {
    const float* in_flow = (const float*)d_in[0];
    const float* gates   = (const float*)d_in[1];
    float* out = (float*)d_out;

    setup_kernel<<<64, SETUP_THREADS>>>(gates);

    cudaLaunchConfig_t cfg = {};
    cfg.gridDim  = dim3(NBLOCKS);
    cfg.blockDim = dim3(256);
    cfg.dynamicSmemBytes = 0;
    cfg.stream = 0;
    cudaLaunchAttribute at[1];
    at[0].id = cudaLaunchAttributeProgrammaticStreamSerialization;
    at[0].val.programmaticStreamSerializationAllowed = 1;
    cfg.attrs = at;
    cfg.numAttrs = 1;
    cudaLaunchKernelEx(&cfg, scatter_kernel, in_flow, out, out_size);
}

// round 8
// speedup vs baseline: 1.0661x; 1.0661x over previous
#include <cuda_runtime.h>
#include <cuda_bf16.h>
#include <cstdint>

#define E_NUM   8
#define N_TOK   8192
#define D_MOD   1024
#define THRESH  0.0f
#define RES_DST 0
#define ROWS_PER_BLOCK 4
#define NBLOCKS ((E_NUM * N_TOK) / ROWS_PER_BLOCK)
#define CHUNK_TOK 1024            /* tokens per setup block */
#define SETUP_THREADS 256
#define TOK_PER_THR (CHUNK_TOK / SETUP_THREADS)   /* 4 */

// Scratch (allocation-free rule: __device__ globals)
__device__ int g_src[E_NUM * N_TOK];   // inverse map: expert e, slot s -> source token
__device__ int g_loads[E_NUM];         // tokens per expert

// ---------------------------------------------------------------------------
// Setup: 8 clusters (one per expert) x 8 CTAs (one per 1024-token chunk).
// Chunk totals exchanged via DSMEM around a cluster barrier -> global prefix.
// Early PDL trigger lets the scatter grid ramp up concurrently.
// ---------------------------------------------------------------------------
__global__ void __launch_bounds__(SETUP_THREADS) __cluster_dims__(8, 1, 1)
setup_kernel(const float* __restrict__ gates, float* __restrict__ out, int out_size) {
#if __CUDA_ARCH__ >= 900
    cudaTriggerProgrammaticLaunchCompletion();   // let scatter blocks start dispatching now
#endif
    const int t = threadIdx.x;
    const int lane = t & 31;
    const int wid  = t >> 5;                 // 0..7
    unsigned int rank;
    asm("mov.u32 %0, %%cluster_ctarank;" : "=r"(rank));   // chunk id 0..7
    const int e = blockIdx.x >> 3;                         // cluster id = expert

    const int tok0 = (int)rank * CHUNK_TOK + t * TOK_PER_THR;

    unsigned int bits = 0;
    #pragma unroll
    for (int i = 0; i < TOK_PER_THR; i++) {
        const float4* gp = (const float4*)(gates + (size_t)(tok0 + i) * E_NUM);
        float4 a = gp[0];
        float4 b = gp[1];
        float g[8] = {a.x, a.y, a.z, a.w, b.x, b.y, b.z, b.w};
        bool m = g[e] > THRESH;
        if (e == RES_DST) {
            bool any = false;
            #pragma unroll
            for (int k = 0; k < 8; k++) any |= (g[k] > THRESH);
            if (!any) m = true;   // residual routing
        }
        bits |= (m ? 1u : 0u) << i;
    }
    const int cnt = __popc(bits);

    int incl = cnt;
    #pragma unroll
    for (int o = 1; o < 32; o <<= 1) {
        int v = __shfl_up_sync(0xffffffffu, incl, o);
        if (lane >= o) incl += v;
    }

    __shared__ int wtot[8];
    __shared__ int wexc[8];
    __shared__ int s_total;      // this CTA's chunk total (DSMEM-exported)
    __shared__ int peer[8];      // peers' chunk totals
    if (lane == 31) wtot[wid] = incl;
    __syncthreads();
    if (t == 0) {
        int run = 0;
        #pragma unroll
        for (int r = 0; r < 8; r++) { int v = wtot[r]; wexc[r] = run; run += v; }
        s_total = run;
    }
    __syncthreads();

    asm volatile("barrier.cluster.arrive.aligned;" ::: "memory");
    asm volatile("barrier.cluster.wait.aligned;"   ::: "memory");

    if (t < 8) {
        unsigned int laddr;
        asm("{ .reg .u64 tt; cvta.to.shared.u64 tt, %1; cvt.u32.u64 %0, tt; }"
            : "=r"(laddr) : "l"(&s_total));
        unsigned int raddr;
        asm("mapa.shared::cluster.u32 %0, %1, %2;" : "=r"(raddr) : "r"(laddr), "r"(t));
        int v;
        asm volatile("ld.shared::cluster.u32 %0, [%1];" : "=r"(v) : "r"(raddr));
        peer[t] = v;
    }
    __syncthreads();

    asm volatile("barrier.cluster.arrive.aligned;" ::: "memory");

    int base = 0, tot = 0;
    #pragma unroll
    for (int r = 0; r < 8; r++) {
        int v = peer[r];
        if (r < (int)rank) base += v;
        tot += v;
    }
    if (rank == 0 && t == 0) {
        g_loads[e] = tot;
        // loads tail of d_out (if the buffer has room for it)
        const long long obase = (long long)E_NUM * N_TOK * D_MOD;
        if (obase + E_NUM <= (long long)out_size) out[obase + e] = (float)tot;
    }

    int off = base + wexc[wid] + (incl - cnt);
    #pragma unroll
    for (int i = 0; i < TOK_PER_THR; i++) {
        if (bits & (1u << i)) {
            g_src[e * N_TOK + off] = tok0 + i;
            off++;
        }
    }

    asm volatile("barrier.cluster.wait.aligned;" ::: "memory");
}

// ---------------------------------------------------------------------------
// Scatter (PDL consumer): proven round-3/6 body. 4 rows per block,
// front-batched loads (MLP=4), streaming __stcs stores.
// ---------------------------------------------------------------------------
__global__ void __launch_bounds__(256) scatter_kernel(const float* __restrict__ in_flow,
                                                      float* __restrict__ out) {
#if __CUDA_ARCH__ >= 900
    cudaGridDependencySynchronize();   // HW wait for setup_kernel completion
#endif

    const int row0 = blockIdx.x * ROWS_PER_BLOCK;   // aligned: rows share one expert
    const int e    = row0 >> 13;                    // / N_TOK
    const int s0   = row0 & (N_TOK - 1);
    const int load = g_loads[e];
    const int tid  = threadIdx.x;

    int  src[ROWS_PER_BLOCK];
    bool val[ROWS_PER_BLOCK];
    #pragma unroll
    for (int i = 0; i < ROWS_PER_BLOCK; i++) {
        val[i] = (s0 + i) < load;
        src[i] = val[i] ? g_src[row0 + i] : 0;
    }

    // Front-batched independent loads (MLP = 4 per thread).
    float4 v[ROWS_PER_BLOCK];
    #pragma unroll
    for (int i = 0; i < ROWS_PER_BLOCK; i++) {
        if (val[i]) {
            const float4* ip = (const float4*)(in_flow + (size_t)src[i] * D_MOD);
            v[i] = ip[tid];
        } else {
            v[i] = make_float4(0.f, 0.f, 0.f, 0.f);
        }
    }

    // Streaming stores: evict-first so in_flow stays L2-resident.
    #pragma unroll
    for (int i = 0; i < ROWS_PER_BLOCK; i++) {
        float4* op = (float4*)(out + (size_t)(row0 + i) * D_MOD);
        __stcs(op + tid, v[i]);
    }
}

extern "C" void kernel_launch(void* const* d_in, const int* in_sizes, int n_in,
                              void* d_out, int out_size) {
    const float* in_flow = (const float*)d_in[0];
    const float* gates   = (const float*)d_in[1];
    float* out = (float*)d_out;

    setup_kernel<<<64, SETUP_THREADS>>>(gates, out, out_size);

    cudaLaunchConfig_t cfg = {};
    cfg.gridDim  = dim3(NBLOCKS);
    cfg.blockDim = dim3(256);
    cfg.dynamicSmemBytes = 0;
    cfg.stream = 0;
    cudaLaunchAttribute at[1];
    at[0].id = cudaLaunchAttributeProgrammaticStreamSerialization;
    at[0].val.programmaticStreamSerializationAllowed = 1;
    cfg.attrs = at;
    cfg.numAttrs = 1;
    cudaLaunchKernelEx(&cfg, scatter_kernel, in_flow, out);
}